// round 12
// baseline (speedup 1.0000x reference)
#include <cuda_runtime.h>
#include <math.h>

#define BB 4
#define TT 2048
#define CC 1024
#define HH 16
#define HS 64

// Scratch (no cudaMalloc allowed)
__device__ float g_q[(size_t)BB * HH * TT * HS];
__device__ float g_k[(size_t)BB * HH * TT * HS];
__device__ float g_v[(size_t)BB * HH * TT * HS];
__device__ float g_att[(size_t)BB * TT * CC];
__device__ float g_wt[(size_t)3 * HH * HS * CC];   // [mat*16+h][n][k], tf32-rounded
__device__ float g_wo[(size_t)CC * CC];            // tf32-rounded Wo (row-major [n][k])

__device__ __forceinline__ float tf32f(float x) {
    unsigned r;
    asm("cvt.rna.tf32.f32 %0, %1;" : "=r"(r) : "f"(x));
    return __uint_as_float(r);
}

__device__ __forceinline__ void mma_tf32(float* c, const unsigned* a, const unsigned* b) {
    asm volatile(
        "mma.sync.aligned.m16n8k8.row.col.f32.tf32.tf32.f32 "
        "{%0,%1,%2,%3},{%4,%5,%6,%7},{%8,%9},{%0,%1,%2,%3};"
        : "+f"(c[0]), "+f"(c[1]), "+f"(c[2]), "+f"(c[3])
        : "r"(a[0]), "r"(a[1]), "r"(a[2]), "r"(a[3]), "r"(b[0]), "r"(b[1]));
}

__device__ __forceinline__ void cp16(void* smem, const void* g) {
    unsigned a = (unsigned)__cvta_generic_to_shared(smem);
    asm volatile("cp.async.ca.shared.global [%0], [%1], 16;" :: "r"(a), "l"(g));
}
#define CP_COMMIT() asm volatile("cp.async.commit_group;")
#define CP_WAIT1()  asm volatile("cp.async.wait_group 1;")

// ---------------------------------------------------------------------------
// Prep 1: transpose + tf32-round QKV weights: W[mat][h][k][n] -> g_wt[ht][n][k]
// grid (48, 16), block 256. 64x64 tile transpose via smem.
// ---------------------------------------------------------------------------
__global__ __launch_bounds__(256) void prep_w(
    const float* __restrict__ Wq, const float* __restrict__ Wk,
    const float* __restrict__ Wv)
{
    __shared__ float t[64][65];
    const int ht  = blockIdx.x;          // mat*16 + h
    const int k0  = blockIdx.y * 64;
    const int mat = ht >> 4, h = ht & 15;
    const float* W = (mat == 0 ? Wq : (mat == 1 ? Wk : Wv)) + (size_t)h * CC * HS;
    const int tid = threadIdx.x;
    #pragma unroll
    for (int i = 0; i < 16; i++) {
        int idx = i * 256 + tid;
        int kk = idx >> 6, nn = idx & 63;
        t[kk][nn] = W[(size_t)(k0 + kk) * HS + nn];
    }
    __syncthreads();
    #pragma unroll
    for (int i = 0; i < 16; i++) {
        int idx = i * 256 + tid;
        int nn = idx >> 6, kk = idx & 63;
        g_wt[((size_t)ht * HS + nn) * CC + k0 + kk] = tf32f(t[kk][nn]);
    }
}

// Prep 2: tf32-round Wo elementwise. grid 1024, block 256 (4 floats/thread).
__global__ __launch_bounds__(256) void prep_wo(const float* __restrict__ Wo)
{
    size_t i = ((size_t)blockIdx.x * 256 + threadIdx.x) * 4;
    float4 v = *(const float4*)(Wo + i);
    float4 r = make_float4(tf32f(v.x), tf32f(v.y), tf32f(v.z), tf32f(v.w));
    *(float4*)(g_wo + i) = r;
}

// ---------------------------------------------------------------------------
// Kernel 1: QKV projection, 2-term tf32 split, wide tile 128x128 (2 heads),
// cp.async double-buffered pipeline. grid = (M/128, 24). Warp tile 32x64.
// Dynamic smem: 2 x (As[128][36] + Bs[128][36]) = 73,728 B.
// ---------------------------------------------------------------------------
__global__ __launch_bounds__(256, 2) void qkv_mma(const float* __restrict__ x)
{
    extern __shared__ float sm[];
    float* Abuf[2] = {sm, sm + 128 * 36};
    float* Bbuf[2] = {sm + 2 * 128 * 36, sm + 3 * 128 * 36};

    const int tid    = threadIdx.x;
    const int warp   = tid >> 5;
    const int lane   = tid & 31;
    const int warp_m = warp >> 1;
    const int warp_n = warp & 1;
    const int mat    = blockIdx.y >> 3;
    const int hpair  = blockIdx.y & 7;
    float* outb      = (mat == 0 ? g_q : (mat == 1 ? g_k : g_v));
    const int m0     = blockIdx.x * 128;

    const int a_row = tid >> 3;         // 0..31
    const int a_kq  = tid & 7;          // 0..7
    const int b_row = tid >> 1;         // 0..127
    const int b_kq0 = (tid & 1) * 4;    // 0 or 4
    const float* bsrc_base = g_wt
        + ((size_t)(mat * HH + 2 * hpair + (b_row >> 6)) * HS + (b_row & 63)) * CC;

    float acc[2][8][4];
    #pragma unroll
    for (int mt = 0; mt < 2; mt++)
        #pragma unroll
        for (int nt = 0; nt < 8; nt++)
            #pragma unroll
            for (int e = 0; e < 4; e++) acc[mt][nt][e] = 0.f;

    // Prologue: fill tile 0
    {
        float* A = Abuf[0]; float* B = Bbuf[0];
        #pragma unroll
        for (int c = 0; c < 4; c++) {
            int row = a_row + 32 * c;
            cp16(&A[row * 36 + a_kq * 4],
                 x + (size_t)(m0 + row) * CC + a_kq * 4);
        }
        #pragma unroll
        for (int c = 0; c < 4; c++) {
            int kq = b_kq0 + c;
            cp16(&B[b_row * 36 + kq * 4], bsrc_base + kq * 4);
        }
        CP_COMMIT();
    }

    for (int it = 0; it < 32; it++) {
        if (it < 31) {
            int k0 = (it + 1) * 32;
            float* A = Abuf[(it + 1) & 1]; float* B = Bbuf[(it + 1) & 1];
            #pragma unroll
            for (int c = 0; c < 4; c++) {
                int row = a_row + 32 * c;
                cp16(&A[row * 36 + a_kq * 4],
                     x + (size_t)(m0 + row) * CC + k0 + a_kq * 4);
            }
            #pragma unroll
            for (int c = 0; c < 4; c++) {
                int kq = b_kq0 + c;
                cp16(&B[b_row * 36 + kq * 4], bsrc_base + k0 + kq * 4);
            }
        }
        CP_COMMIT();
        CP_WAIT1();
        __syncthreads();

        const float* As = Abuf[it & 1];
        const float* Bs = Bbuf[it & 1];
        #pragma unroll
        for (int kk8 = 0; kk8 < 4; kk8++) {
            const int kc = kk8 * 8 + (lane & 3);
            unsigned ah[2][4], al[2][4], bh[8][2];
            #pragma unroll
            for (int mt = 0; mt < 2; mt++) {
                int r = warp_m * 32 + mt * 16 + (lane >> 2);
                float q0 = As[r * 36 + kc], q1 = As[(r + 8) * 36 + kc];
                float q2 = As[r * 36 + kc + 4], q3 = As[(r + 8) * 36 + kc + 4];
                float h0 = tf32f(q0), h1 = tf32f(q1), h2 = tf32f(q2), h3 = tf32f(q3);
                ah[mt][0] = __float_as_uint(h0); al[mt][0] = __float_as_uint(q0 - h0);
                ah[mt][1] = __float_as_uint(h1); al[mt][1] = __float_as_uint(q1 - h1);
                ah[mt][2] = __float_as_uint(h2); al[mt][2] = __float_as_uint(q2 - h2);
                ah[mt][3] = __float_as_uint(h3); al[mt][3] = __float_as_uint(q3 - h3);
            }
            #pragma unroll
            for (int nt = 0; nt < 8; nt++) {
                int n = warp_n * 64 + nt * 8 + (lane >> 2);
                bh[nt][0] = __float_as_uint(Bs[n * 36 + kc]);
                bh[nt][1] = __float_as_uint(Bs[n * 36 + kc + 4]);
            }
            #pragma unroll
            for (int mt = 0; mt < 2; mt++)
                #pragma unroll
                for (int nt = 0; nt < 8; nt++) {
                    mma_tf32(acc[mt][nt], ah[mt], bh[nt]);
                    mma_tf32(acc[mt][nt], al[mt], bh[nt]);
                }
        }
        __syncthreads();
    }

    // Epilogue: write [B,H,T,HS], head = 2*hpair + (col>>6)
    #pragma unroll
    for (int mt = 0; mt < 2; mt++)
        #pragma unroll
        for (int nt = 0; nt < 8; nt++)
            #pragma unroll
            for (int half = 0; half < 2; half++) {
                int m = m0 + warp_m * 32 + mt * 16 + (lane >> 2) + half * 8;
                int col = warp_n * 64 + nt * 8 + (lane & 3) * 2;
                int head = 2 * hpair + (col >> 6);
                int hcol = col & (HS - 1);
                int b_ = m >> 11, t = m & (TT - 1);
                float* p = outb + ((size_t)((b_ * HH + head) * TT + t)) * HS + hcol;
                *(float2*)p = make_float2(acc[mt][nt][half * 2], acc[mt][nt][half * 2 + 1]);
            }
}

// ---------------------------------------------------------------------------
// Kernel 2: flash attention (unchanged from R10/R11 — protected win).
// ---------------------------------------------------------------------------
#define QS_STR 68
#define KP_STR 74
#define VP_STR 42
#define PH_STR 36

__global__ __launch_bounds__(256) void attn_mma()
{
    extern __shared__ float sm[];
    float* Qs  = sm;
    float* Khp = Qs + 128 * QS_STR;
    float* Vhp = Khp + 32 * KP_STR;
    float* Ph  = Vhp + 64 * VP_STR;

    const int tid  = threadIdx.x;
    const int lane = tid & 31;
    const int warp = tid >> 5;
    const int bh   = blockIdx.x;
    const int qi   = (int)(gridDim.y - 1 - blockIdx.y);
    const int b    = bh >> 4, h = bh & 15;
    const int q0g  = qi * 128;
    const int r_lo = warp * 16 + (lane >> 2);

    {
        int q = tid >> 1, dbase = (tid & 1) * 32;
        const float* qp = g_q + ((size_t)bh * TT + q0g + q) * HS + dbase;
        #pragma unroll
        for (int c = 0; c < 8; c++)
            *(float4*)&Qs[q * QS_STR + dbase + c * 4] = *(const float4*)(qp + c * 4);
    }

    float m_run[2] = {-1e30f, -1e30f};
    float l_run[2] = {0.f, 0.f};
    float acc_o[8][4];
    #pragma unroll
    for (int nt = 0; nt < 8; nt++)
        #pragma unroll
        for (int e = 0; e < 4; e++) acc_o[nt][e] = 0.f;

    const int nb   = 4 * qi + 4;
    const int wmax = q0g + warp * 16 + 15;

    for (int j = 0; j < nb; j++) {
        __syncthreads();
        {
            int s = tid >> 3, d0 = (tid & 7) * 8;
            const float* kp = g_k + ((size_t)bh * TT + j * 32 + s) * HS + d0;
            const float* vp = g_v + ((size_t)bh * TT + j * 32 + s) * HS + d0;
            float4 ka = *(const float4*)(kp), kb = *(const float4*)(kp + 4);
            float kv[8] = {ka.x, ka.y, ka.z, ka.w, kb.x, kb.y, kb.z, kb.w};
            int kbase = s * KP_STR + d0;
            #pragma unroll
            for (int c = 0; c < 4; c++)
                *(float2*)&Khp[kbase + c * 2] =
                    make_float2(tf32f(kv[c]), tf32f(kv[c + 4]));
            float4 va = *(const float4*)(vp), vb = *(const float4*)(vp + 4);
            float vv[8] = {va.x, va.y, va.z, va.w, vb.x, vb.y, vb.z, vb.w};
            int vslot = (s >> 3) * 8 + (s & 3) * 2 + ((s >> 2) & 1);
            #pragma unroll
            for (int e = 0; e < 8; e++)
                Vhp[(d0 + e) * VP_STR + vslot] = tf32f(vv[e]);
        }
        __syncthreads();

        if (j * 32 <= wmax) {
            float accs[4][4];
            #pragma unroll
            for (int nt = 0; nt < 4; nt++)
                #pragma unroll
                for (int e = 0; e < 4; e++) accs[nt][e] = 0.f;

            #pragma unroll
            for (int k8 = 0; k8 < 8; k8++) {
                const int kc = k8 * 8 + (lane & 3);
                float q0 = Qs[r_lo * QS_STR + kc];
                float q1 = Qs[(r_lo + 8) * QS_STR + kc];
                float q2 = Qs[r_lo * QS_STR + kc + 4];
                float q3 = Qs[(r_lo + 8) * QS_STR + kc + 4];
                float h0 = tf32f(q0), h1 = tf32f(q1), h2 = tf32f(q2), h3 = tf32f(q3);
                unsigned ah[4] = {__float_as_uint(h0), __float_as_uint(h1),
                                  __float_as_uint(h2), __float_as_uint(h3)};
                unsigned al[4] = {__float_as_uint(q0 - h0), __float_as_uint(q1 - h1),
                                  __float_as_uint(q2 - h2), __float_as_uint(q3 - h3)};
                #pragma unroll
                for (int nt = 0; nt < 4; nt++) {
                    int n = nt * 8 + (lane >> 2);
                    float2 b2h = *(float2*)&Khp[n * KP_STR + k8 * 8 + (lane & 3) * 2];
                    unsigned bh2[2] = {__float_as_uint(b2h.x), __float_as_uint(b2h.y)};
                    mma_tf32(accs[nt], ah, bh2);
                    mma_tf32(accs[nt], al, bh2);
                }
            }

            const bool domask = (j >= 4 * qi);
            #pragma unroll
            for (int half = 0; half < 2; half++) {
                const int tq = q0g + warp * 16 + (lane >> 2) + half * 8;
                float sv[4][2];
                float mx = -1e30f;
                #pragma unroll
                for (int nt = 0; nt < 4; nt++)
                    #pragma unroll
                    for (int e2 = 0; e2 < 2; e2++) {
                        float v = accs[nt][half * 2 + e2] * 0.125f;
                        int col = j * 32 + nt * 8 + (lane & 3) * 2 + e2;
                        if (domask && col > tq) v = -1e30f;
                        sv[nt][e2] = v;
                        mx = fmaxf(mx, v);
                    }
                mx = fmaxf(mx, __shfl_xor_sync(0xffffffffu, mx, 1));
                mx = fmaxf(mx, __shfl_xor_sync(0xffffffffu, mx, 2));
                float mn = fmaxf(m_run[half], mx);
                float cf = __expf(m_run[half] - mn);
                m_run[half] = mn;
                float ps = 0.f;
                #pragma unroll
                for (int nt = 0; nt < 4; nt++) {
                    #pragma unroll
                    for (int e2 = 0; e2 < 2; e2++) {
                        float p = __expf(sv[nt][e2] - mn);
                        sv[nt][e2] = p;
                        ps += p;
                    }
                    *(float2*)&Ph[(warp * 16 + (lane >> 2) + half * 8) * PH_STR
                                  + nt * 8 + (lane & 3) * 2] =
                        make_float2(tf32f(sv[nt][0]), tf32f(sv[nt][1]));
                }
                ps += __shfl_xor_sync(0xffffffffu, ps, 1);
                ps += __shfl_xor_sync(0xffffffffu, ps, 2);
                l_run[half] = l_run[half] * cf + ps;
                #pragma unroll
                for (int nt = 0; nt < 8; nt++) {
                    acc_o[nt][half * 2] *= cf;
                    acc_o[nt][half * 2 + 1] *= cf;
                }
            }
            __syncwarp();

            #pragma unroll
            for (int k8s = 0; k8s < 4; k8s++) {
                const int kcs = k8s * 8 + (lane & 3);
                unsigned a[4] = {
                    __float_as_uint(Ph[r_lo * PH_STR + kcs]),
                    __float_as_uint(Ph[(r_lo + 8) * PH_STR + kcs]),
                    __float_as_uint(Ph[r_lo * PH_STR + kcs + 4]),
                    __float_as_uint(Ph[(r_lo + 8) * PH_STR + kcs + 4])};
                #pragma unroll
                for (int nt = 0; nt < 8; nt++) {
                    int n = nt * 8 + (lane >> 2);
                    float2 v2h = *(float2*)&Vhp[n * VP_STR + k8s * 8 + (lane & 3) * 2];
                    unsigned vh2[2] = {__float_as_uint(v2h.x), __float_as_uint(v2h.y)};
                    mma_tf32(acc_o[nt], a, vh2);
                }
            }
        }
    }

    #pragma unroll
    for (int half = 0; half < 2; half++) {
        float inv = 1.f / l_run[half];
        int tq = q0g + warp * 16 + (lane >> 2) + half * 8;
        #pragma unroll
        for (int nt = 0; nt < 8; nt++) {
            int col = h * HS + nt * 8 + (lane & 3) * 2;
            float* op = g_att + ((size_t)(b * TT + tq)) * CC + col;
            *(float2*)op = make_float2(acc_o[nt][half * 2] * inv,
                                       acc_o[nt][half * 2 + 1] * inv);
        }
    }
}

// ---------------------------------------------------------------------------
// Kernel 3: output projection, wide tile 128x128, cp.async double-buffered.
// grid = (M/128, 8). Dynamic smem 73,728 B.
// ---------------------------------------------------------------------------
__global__ __launch_bounds__(256, 2) void proj_mma(
    const float* __restrict__ bo, float* __restrict__ out)
{
    extern __shared__ float sm[];
    float* Abuf[2] = {sm, sm + 128 * 36};
    float* Bbuf[2] = {sm + 2 * 128 * 36, sm + 3 * 128 * 36};

    const int tid    = threadIdx.x;
    const int warp   = tid >> 5;
    const int lane   = tid & 31;
    const int warp_m = warp >> 1;
    const int warp_n = warp & 1;
    const int m0     = blockIdx.x * 128;
    const int n0     = blockIdx.y * 128;

    const int a_row = tid >> 3;
    const int a_kq  = tid & 7;
    const int b_row = tid >> 1;
    const int b_kq0 = (tid & 1) * 4;
    const float* bsrc_base = g_wo + (size_t)(n0 + b_row) * CC;

    float acc[2][8][4];
    #pragma unroll
    for (int mt = 0; mt < 2; mt++)
        #pragma unroll
        for (int nt = 0; nt < 8; nt++)
            #pragma unroll
            for (int e = 0; e < 4; e++) acc[mt][nt][e] = 0.f;

    {
        float* A = Abuf[0]; float* B = Bbuf[0];
        #pragma unroll
        for (int c = 0; c < 4; c++) {
            int row = a_row + 32 * c;
            cp16(&A[row * 36 + a_kq * 4],
                 g_att + (size_t)(m0 + row) * CC + a_kq * 4);
        }
        #pragma unroll
        for (int c = 0; c < 4; c++) {
            int kq = b_kq0 + c;
            cp16(&B[b_row * 36 + kq * 4], bsrc_base + kq * 4);
        }
        CP_COMMIT();
    }

    for (int it = 0; it < 32; it++) {
        if (it < 31) {
            int k0 = (it + 1) * 32;
            float* A = Abuf[(it + 1) & 1]; float* B = Bbuf[(it + 1) & 1];
            #pragma unroll
            for (int c = 0; c < 4; c++) {
                int row = a_row + 32 * c;
                cp16(&A[row * 36 + a_kq * 4],
                     g_att + (size_t)(m0 + row) * CC + k0 + a_kq * 4);
            }
            #pragma unroll
            for (int c = 0; c < 4; c++) {
                int kq = b_kq0 + c;
                cp16(&B[b_row * 36 + kq * 4], bsrc_base + k0 + kq * 4);
            }
        }
        CP_COMMIT();
        CP_WAIT1();
        __syncthreads();

        const float* As = Abuf[it & 1];
        const float* Bs = Bbuf[it & 1];
        #pragma unroll
        for (int kk8 = 0; kk8 < 4; kk8++) {
            const int kc = kk8 * 8 + (lane & 3);
            unsigned ah[2][4], al[2][4], bh[8][2];
            #pragma unroll
            for (int mt = 0; mt < 2; mt++) {
                int r = warp_m * 32 + mt * 16 + (lane >> 2);
                float q0 = As[r * 36 + kc], q1 = As[(r + 8) * 36 + kc];
                float q2 = As[r * 36 + kc + 4], q3 = As[(r + 8) * 36 + kc + 4];
                float h0 = tf32f(q0), h1 = tf32f(q1), h2 = tf32f(q2), h3 = tf32f(q3);
                ah[mt][0] = __float_as_uint(h0); al[mt][0] = __float_as_uint(q0 - h0);
                ah[mt][1] = __float_as_uint(h1); al[mt][1] = __float_as_uint(q1 - h1);
                ah[mt][2] = __float_as_uint(h2); al[mt][2] = __float_as_uint(q2 - h2);
                ah[mt][3] = __float_as_uint(h3); al[mt][3] = __float_as_uint(q3 - h3);
            }
            #pragma unroll
            for (int nt = 0; nt < 8; nt++) {
                int n = warp_n * 64 + nt * 8 + (lane >> 2);
                bh[nt][0] = __float_as_uint(Bs[n * 36 + kc]);
                bh[nt][1] = __float_as_uint(Bs[n * 36 + kc + 4]);
            }
            #pragma unroll
            for (int mt = 0; mt < 2; mt++)
                #pragma unroll
                for (int nt = 0; nt < 8; nt++) {
                    mma_tf32(acc[mt][nt], ah[mt], bh[nt]);
                    mma_tf32(acc[mt][nt], al[mt], bh[nt]);
                }
        }
        __syncthreads();
    }

    #pragma unroll
    for (int mt = 0; mt < 2; mt++)
        #pragma unroll
        for (int nt = 0; nt < 8; nt++)
            #pragma unroll
            for (int half = 0; half < 2; half++) {
                int m = m0 + warp_m * 32 + mt * 16 + (lane >> 2) + half * 8;
                int n = n0 + warp_n * 64 + nt * 8 + (lane & 3) * 2;
                float b0 = __ldg(bo + n), b1 = __ldg(bo + n + 1);
                float* p = out + (size_t)m * CC + n;
                *(float2*)p = make_float2(acc[mt][nt][half * 2] + b0,
                                          acc[mt][nt][half * 2 + 1] + b1);
            }
}

extern "C" void kernel_launch(void* const* d_in, const int* in_sizes, int n_in,
                              void* d_out, int out_size)
{
    const float* x  = (const float*)d_in[0];
    const float* Wq = (const float*)d_in[1];
    const float* Wk = (const float*)d_in[2];
    const float* Wv = (const float*)d_in[3];
    const float* Wo = (const float*)d_in[4];
    const float* bo = (const float*)d_in[5];
    float* out = (float*)d_out;

    (void)in_sizes; (void)n_in; (void)out_size;

    // 0) Weight prep (transpose + tf32 round)
    prep_w<<<dim3(48, 16), 256>>>(Wq, Wk, Wv);
    prep_wo<<<1024, 256>>>(Wo);

    // 1) QKV projections (cp.async double-buffered, 73,728 B dynamic smem)
    const int gemm_smem = 4 * 128 * 36 * 4;
    cudaFuncSetAttribute(qkv_mma, cudaFuncAttributeMaxDynamicSharedMemorySize,
                         gemm_smem);
    qkv_mma<<<dim3(64, 24), 256, gemm_smem>>>(x);

    // 2) Flash attention (unchanged R10)
    const int attn_smem = (128 * QS_STR + 32 * KP_STR + 64 * VP_STR
                           + 128 * PH_STR) * 4;
    cudaFuncSetAttribute(attn_mma, cudaFuncAttributeMaxDynamicSharedMemorySize,
                         attn_smem);
    attn_mma<<<dim3(64, 16), 256, attn_smem>>>();

    // 3) Output projection + bias (cp.async double-buffered)
    cudaFuncSetAttribute(proj_mma, cudaFuncAttributeMaxDynamicSharedMemorySize,
                         gemm_smem);
    proj_mma<<<dim3(64, 8), 256, gemm_smem>>>(bo, out);
}

// round 15
// speedup vs baseline: 1.0583x; 1.0583x over previous
#include <cuda_runtime.h>
#include <math.h>

#define BB 4
#define TT 2048
#define CC 1024
#define HH 16
#define HS 64

// Scratch (no cudaMalloc allowed)
__device__ float g_q[(size_t)BB * HH * TT * HS];
__device__ float g_k[(size_t)BB * HH * TT * HS];
__device__ float g_v[(size_t)BB * HH * TT * HS];
__device__ float g_att[(size_t)BB * TT * CC];

__device__ __forceinline__ float tf32f(float x) {
    unsigned r;
    asm("cvt.rna.tf32.f32 %0, %1;" : "=r"(r) : "f"(x));
    return __uint_as_float(r);
}

__device__ __forceinline__ void mma_tf32(float* c, const unsigned* a, const unsigned* b) {
    asm volatile(
        "mma.sync.aligned.m16n8k8.row.col.f32.tf32.tf32.f32 "
        "{%0,%1,%2,%3},{%4,%5,%6,%7},{%8,%9},{%0,%1,%2,%3};"
        : "+f"(c[0]), "+f"(c[1]), "+f"(c[2]), "+f"(c[3])
        : "r"(a[0]), "r"(a[1]), "r"(a[2]), "r"(a[3]), "r"(b[0]), "r"(b[1]));
}

// ---------------------------------------------------------------------------
// Kernel 1: QKV projection (R11 form — measured best). Wide tile 128x128
// (2 heads/block). Warp grid 4x2, warp tile 32x64.
// grid = (M/128, 3 mats * 8 head-pairs).
// ---------------------------------------------------------------------------
__global__ __launch_bounds__(256, 2) void qkv_mma(
    const float* __restrict__ x,
    const float* __restrict__ Wq,
    const float* __restrict__ Wk,
    const float* __restrict__ Wv)
{
    __shared__ float As[128][36];   // fp32 A
    __shared__ float Bh[128][37];   // tf32 B [n][k], 2 heads stacked

    const int tid    = threadIdx.x;
    const int warp   = tid >> 5;
    const int lane   = tid & 31;
    const int warp_m = warp >> 1;
    const int warp_n = warp & 1;
    const int mat    = blockIdx.y >> 3;
    const int hpair  = blockIdx.y & 7;
    const float* Wm  = (mat == 0 ? Wq : (mat == 1 ? Wk : Wv))
                       + (size_t)(2 * hpair) * CC * HS;
    float* outb      = (mat == 0 ? g_q : (mat == 1 ? g_k : g_v));
    const int m0     = blockIdx.x * 128;

    float acc[2][8][4];
    #pragma unroll
    for (int mt = 0; mt < 2; mt++)
        #pragma unroll
        for (int nt = 0; nt < 8; nt++)
            #pragma unroll
            for (int e = 0; e < 4; e++) acc[mt][nt][e] = 0.f;

    const int a_row = tid >> 3;
    const int a_kq  = tid & 7;
    const int b_kk  = tid >> 3;
    const int b_n8  = tid & 7;

    for (int k0 = 0; k0 < CC; k0 += 32) {
        #pragma unroll
        for (int c = 0; c < 4; c++) {
            int row = a_row + 32 * c;
            float4 v = *(const float4*)(x + (size_t)(m0 + row) * CC + k0 + a_kq * 4);
            As[row][a_kq * 4 + 0] = v.x;
            As[row][a_kq * 4 + 1] = v.y;
            As[row][a_kq * 4 + 2] = v.z;
            As[row][a_kq * 4 + 3] = v.w;
        }
        #pragma unroll
        for (int hp = 0; hp < 2; hp++) {
            const float* wp = Wm + (size_t)hp * CC * HS
                              + (size_t)(k0 + b_kk) * HS + b_n8 * 8;
            float4 v0 = *(const float4*)(wp);
            float4 v1 = *(const float4*)(wp + 4);
            float vv[8] = {v0.x, v0.y, v0.z, v0.w, v1.x, v1.y, v1.z, v1.w};
            #pragma unroll
            for (int e = 0; e < 8; e++)
                Bh[hp * 64 + b_n8 * 8 + e][b_kk] = tf32f(vv[e]);
        }
        __syncthreads();

        #pragma unroll
        for (int kk8 = 0; kk8 < 4; kk8++) {
            const int kc = kk8 * 8 + (lane & 3);
            unsigned ah[2][4], al[2][4], bh[8][2];
            #pragma unroll
            for (int mt = 0; mt < 2; mt++) {
                int r = warp_m * 32 + mt * 16 + (lane >> 2);
                float q0 = As[r][kc], q1 = As[r + 8][kc];
                float q2 = As[r][kc + 4], q3 = As[r + 8][kc + 4];
                float h0 = tf32f(q0), h1 = tf32f(q1), h2 = tf32f(q2), h3 = tf32f(q3);
                ah[mt][0] = __float_as_uint(h0); al[mt][0] = __float_as_uint(q0 - h0);
                ah[mt][1] = __float_as_uint(h1); al[mt][1] = __float_as_uint(q1 - h1);
                ah[mt][2] = __float_as_uint(h2); al[mt][2] = __float_as_uint(q2 - h2);
                ah[mt][3] = __float_as_uint(h3); al[mt][3] = __float_as_uint(q3 - h3);
            }
            #pragma unroll
            for (int nt = 0; nt < 8; nt++) {
                int n = warp_n * 64 + nt * 8 + (lane >> 2);
                bh[nt][0] = __float_as_uint(Bh[n][kc]);
                bh[nt][1] = __float_as_uint(Bh[n][kc + 4]);
            }
            #pragma unroll
            for (int mt = 0; mt < 2; mt++)
                #pragma unroll
                for (int nt = 0; nt < 8; nt++) {
                    mma_tf32(acc[mt][nt], ah[mt], bh[nt]);
                    mma_tf32(acc[mt][nt], al[mt], bh[nt]);
                }
        }
        __syncthreads();
    }

    #pragma unroll
    for (int mt = 0; mt < 2; mt++)
        #pragma unroll
        for (int nt = 0; nt < 8; nt++)
            #pragma unroll
            for (int half = 0; half < 2; half++) {
                int m = m0 + warp_m * 32 + mt * 16 + (lane >> 2) + half * 8;
                int col = warp_n * 64 + nt * 8 + (lane & 3) * 2;
                int head = 2 * hpair + (col >> 6);
                int hcol = col & (HS - 1);
                int b_ = m >> 11, t = m & (TT - 1);
                float* p = outb + ((size_t)((b_ * HH + head) * TT + t)) * HS + hcol;
                *(float2*)p = make_float2(acc[mt][nt][half * 2], acc[mt][nt][half * 2 + 1]);
            }
}

// ---------------------------------------------------------------------------
// Kernel 2: flash attention, tf32 MMA. PV A-fragments come straight
// from softmax registers; V stored at NATURAL k-position so the float2
// B-read pairs k-slot q with s=2q / q+4 with s=2q+1 (matches the S-accum
// layout). Ph smem removed entirely.
// grid = (B*H, 16). 8 warps x 16 q-rows. kv-block 32.
// smem: Qs 34,816 | Khp 9,472 | Vhp 10,752 = 55,040 B
// ---------------------------------------------------------------------------
#define QS_STR 68
#define KP_STR 74
#define VP_STR 42

__global__ __launch_bounds__(256) void attn_mma()
{
    extern __shared__ float sm[];
    float* Qs  = sm;                        // 128*68
    float* Khp = Qs + 128 * QS_STR;         // 32*74 (tf32 hi pairs)
    float* Vhp = Khp + 32 * KP_STR;         // 64*42 (tf32 hi, [d][s] natural)

    const int tid  = threadIdx.x;
    const int lane = tid & 31;
    const int warp = tid >> 5;
    const int bh   = blockIdx.x;
    const int qi   = (int)(gridDim.y - 1 - blockIdx.y);   // heavy tiles first
    const int b    = bh >> 4, h = bh & 15;
    const int q0g  = qi * 128;
    const int r_lo = warp * 16 + (lane >> 2);

    // Load Q tile (fp32)
    {
        int q = tid >> 1, dbase = (tid & 1) * 32;
        const float* qp = g_q + ((size_t)bh * TT + q0g + q) * HS + dbase;
        #pragma unroll
        for (int c = 0; c < 8; c++)
            *(float4*)&Qs[q * QS_STR + dbase + c * 4] = *(const float4*)(qp + c * 4);
    }

    float m_run[2] = {-1e30f, -1e30f};
    float l_run[2] = {0.f, 0.f};
    float acc_o[8][4];
    #pragma unroll
    for (int nt = 0; nt < 8; nt++)
        #pragma unroll
        for (int e = 0; e < 4; e++) acc_o[nt][e] = 0.f;

    const int nb   = 4 * qi + 4;
    const int wmax = q0g + warp * 16 + 15;

    for (int j = 0; j < nb; j++) {
        __syncthreads();    // prior block's reads done (covers Q store at j=0)
        // Fill K (tf32 hi, packed pairs) and V (transposed tf32 hi, NATURAL s)
        {
            int s = tid >> 3, d0 = (tid & 7) * 8;
            const float* kp = g_k + ((size_t)bh * TT + j * 32 + s) * HS + d0;
            const float* vp = g_v + ((size_t)bh * TT + j * 32 + s) * HS + d0;
            float4 ka = *(const float4*)(kp), kb = *(const float4*)(kp + 4);
            float kv[8] = {ka.x, ka.y, ka.z, ka.w, kb.x, kb.y, kb.z, kb.w};
            int kbase = s * KP_STR + d0;
            #pragma unroll
            for (int c = 0; c < 4; c++)
                *(float2*)&Khp[kbase + c * 2] =
                    make_float2(tf32f(kv[c]), tf32f(kv[c + 4]));
            float4 va = *(const float4*)(vp), vb = *(const float4*)(vp + 4);
            float vv[8] = {va.x, va.y, va.z, va.w, vb.x, vb.y, vb.z, vb.w};
            #pragma unroll
            for (int e = 0; e < 8; e++)
                Vhp[(d0 + e) * VP_STR + s] = tf32f(vv[e]);
        }
        __syncthreads();

        if (j * 32 <= wmax) {
            // ---- S = Q K^T (2-term: (Qh+Ql) x Kh; Q split at read) ----
            float accs[4][4];
            #pragma unroll
            for (int nt = 0; nt < 4; nt++)
                #pragma unroll
                for (int e = 0; e < 4; e++) accs[nt][e] = 0.f;

            #pragma unroll
            for (int k8 = 0; k8 < 8; k8++) {
                const int kc = k8 * 8 + (lane & 3);
                float q0 = Qs[r_lo * QS_STR + kc];
                float q1 = Qs[(r_lo + 8) * QS_STR + kc];
                float q2 = Qs[r_lo * QS_STR + kc + 4];
                float q3 = Qs[(r_lo + 8) * QS_STR + kc + 4];
                float h0 = tf32f(q0), h1 = tf32f(q1), h2 = tf32f(q2), h3 = tf32f(q3);
                unsigned ah[4] = {__float_as_uint(h0), __float_as_uint(h1),
                                  __float_as_uint(h2), __float_as_uint(h3)};
                unsigned al[4] = {__float_as_uint(q0 - h0), __float_as_uint(q1 - h1),
                                  __float_as_uint(q2 - h2), __float_as_uint(q3 - h3)};
                #pragma unroll
                for (int nt = 0; nt < 4; nt++) {
                    int n = nt * 8 + (lane >> 2);
                    float2 b2h = *(float2*)&Khp[n * KP_STR + k8 * 8 + (lane & 3) * 2];
                    unsigned bh2[2] = {__float_as_uint(b2h.x), __float_as_uint(b2h.y)};
                    mma_tf32(accs[nt], ah, bh2);
                    mma_tf32(accs[nt], al, bh2);
                }
            }

            // ---- online softmax (rows warp-local); build PV A-frags in regs
            const bool domask = (j >= 4 * qi);
            unsigned a_pv[4][4];   // [k-group nt][frag reg]
            #pragma unroll
            for (int half = 0; half < 2; half++) {
                const int tq = q0g + warp * 16 + (lane >> 2) + half * 8;
                float sv[4][2];
                float mx = -1e30f;
                #pragma unroll
                for (int nt = 0; nt < 4; nt++)
                    #pragma unroll
                    for (int e2 = 0; e2 < 2; e2++) {
                        float v = accs[nt][half * 2 + e2] * 0.125f;
                        int col = j * 32 + nt * 8 + (lane & 3) * 2 + e2;
                        if (domask && col > tq) v = -1e30f;
                        sv[nt][e2] = v;
                        mx = fmaxf(mx, v);
                    }
                mx = fmaxf(mx, __shfl_xor_sync(0xffffffffu, mx, 1));
                mx = fmaxf(mx, __shfl_xor_sync(0xffffffffu, mx, 2));
                float mn = fmaxf(m_run[half], mx);
                float cf = __expf(m_run[half] - mn);
                m_run[half] = mn;
                float ps = 0.f;
                #pragma unroll
                for (int nt = 0; nt < 4; nt++) {
                    #pragma unroll
                    for (int e2 = 0; e2 < 2; e2++) {
                        float p = __expf(sv[nt][e2] - mn);
                        sv[nt][e2] = p;
                        ps += p;
                    }
                    // A-frag: a[half] = col 2q value, a[2+half] = col 2q+1
                    a_pv[nt][half]     = __float_as_uint(tf32f(sv[nt][0]));
                    a_pv[nt][2 + half] = __float_as_uint(tf32f(sv[nt][1]));
                }
                ps += __shfl_xor_sync(0xffffffffu, ps, 1);
                ps += __shfl_xor_sync(0xffffffffu, ps, 2);
                l_run[half] = l_run[half] * cf + ps;
                #pragma unroll
                for (int nt = 0; nt < 8; nt++) {
                    acc_o[nt][half * 2] *= cf;
                    acc_o[nt][half * 2 + 1] *= cf;
                }
            }

            // ---- O += P V (1-term; A from registers, B natural-s float2) ----
            #pragma unroll
            for (int ntk = 0; ntk < 4; ntk++) {
                #pragma unroll
                for (int nt = 0; nt < 8; nt++) {
                    int n = nt * 8 + (lane >> 2);
                    float2 v2h = *(float2*)&Vhp[n * VP_STR + ntk * 8 + (lane & 3) * 2];
                    unsigned vh2[2] = {__float_as_uint(v2h.x), __float_as_uint(v2h.y)};
                    mma_tf32(acc_o[nt], a_pv[ntk], vh2);
                }
            }
        }
    }

    // Epilogue: normalize, write [B,T,C]
    #pragma unroll
    for (int half = 0; half < 2; half++) {
        float inv = 1.f / l_run[half];
        int tq = q0g + warp * 16 + (lane >> 2) + half * 8;
        #pragma unroll
        for (int nt = 0; nt < 8; nt++) {
            int col = h * HS + nt * 8 + (lane & 3) * 2;
            float* op = g_att + ((size_t)(b * TT + tq)) * CC + col;
            *(float2*)op = make_float2(acc_o[nt][half * 2] * inv,
                                       acc_o[nt][half * 2 + 1] * inv);
        }
    }
}

// ---------------------------------------------------------------------------
// Kernel 3: output projection (R11 form). Wide tile 128x128, warp tile 32x64.
// grid = (M/128, N/128).
// ---------------------------------------------------------------------------
__global__ __launch_bounds__(256, 2) void proj_mma(
    const float* __restrict__ Wo,
    const float* __restrict__ bo,
    float* __restrict__ out)
{
    __shared__ float As[128][36];
    __shared__ float Bh[128][36];

    const int tid    = threadIdx.x;
    const int warp   = tid >> 5;
    const int lane   = tid & 31;
    const int warp_m = warp >> 1;
    const int warp_n = warp & 1;
    const int m0     = blockIdx.x * 128;
    const int n0     = blockIdx.y * 128;

    float acc[2][8][4];
    #pragma unroll
    for (int mt = 0; mt < 2; mt++)
        #pragma unroll
        for (int nt = 0; nt < 8; nt++)
            #pragma unroll
            for (int e = 0; e < 4; e++) acc[mt][nt][e] = 0.f;

    const int a_row = tid >> 3;
    const int a_kq  = tid & 7;
    const int b_n   = tid >> 2;
    const int b_kq  = tid & 3;

    for (int k0 = 0; k0 < CC; k0 += 32) {
        #pragma unroll
        for (int c = 0; c < 4; c++) {
            int row = a_row + 32 * c;
            float4 v = *(const float4*)(g_att + (size_t)(m0 + row) * CC + k0 + a_kq * 4);
            As[row][a_kq * 4 + 0] = v.x;
            As[row][a_kq * 4 + 1] = v.y;
            As[row][a_kq * 4 + 2] = v.z;
            As[row][a_kq * 4 + 3] = v.w;
        }
        #pragma unroll
        for (int np = 0; np < 2; np++) {
            int n = np * 64 + b_n;
            const float* wp = Wo + (size_t)(n0 + n) * CC + k0 + b_kq * 8;
            float4 v0 = *(const float4*)(wp);
            float4 v1 = *(const float4*)(wp + 4);
            float vv[8] = {v0.x, v0.y, v0.z, v0.w, v1.x, v1.y, v1.z, v1.w};
            #pragma unroll
            for (int e = 0; e < 8; e++)
                Bh[n][b_kq * 8 + e] = tf32f(vv[e]);
        }
        __syncthreads();

        #pragma unroll
        for (int kk8 = 0; kk8 < 4; kk8++) {
            const int kc = kk8 * 8 + (lane & 3);
            unsigned ah[2][4], al[2][4], bh[8][2];
            #pragma unroll
            for (int mt = 0; mt < 2; mt++) {
                int r = warp_m * 32 + mt * 16 + (lane >> 2);
                float q0 = As[r][kc], q1 = As[r + 8][kc];
                float q2 = As[r][kc + 4], q3 = As[r + 8][kc + 4];
                float h0 = tf32f(q0), h1 = tf32f(q1), h2 = tf32f(q2), h3 = tf32f(q3);
                ah[mt][0] = __float_as_uint(h0); al[mt][0] = __float_as_uint(q0 - h0);
                ah[mt][1] = __float_as_uint(h1); al[mt][1] = __float_as_uint(q1 - h1);
                ah[mt][2] = __float_as_uint(h2); al[mt][2] = __float_as_uint(q2 - h2);
                ah[mt][3] = __float_as_uint(h3); al[mt][3] = __float_as_uint(q3 - h3);
            }
            #pragma unroll
            for (int nt = 0; nt < 8; nt++) {
                int n = warp_n * 64 + nt * 8 + (lane >> 2);
                bh[nt][0] = __float_as_uint(Bh[n][kc]);
                bh[nt][1] = __float_as_uint(Bh[n][kc + 4]);
            }
            #pragma unroll
            for (int mt = 0; mt < 2; mt++)
                #pragma unroll
                for (int nt = 0; nt < 8; nt++) {
                    mma_tf32(acc[mt][nt], ah[mt], bh[nt]);
                    mma_tf32(acc[mt][nt], al[mt], bh[nt]);
                }
        }
        __syncthreads();
    }

    #pragma unroll
    for (int mt = 0; mt < 2; mt++)
        #pragma unroll
        for (int nt = 0; nt < 8; nt++)
            #pragma unroll
            for (int half = 0; half < 2; half++) {
                int m = m0 + warp_m * 32 + mt * 16 + (lane >> 2) + half * 8;
                int n = n0 + warp_n * 64 + nt * 8 + (lane & 3) * 2;
                float b0 = __ldg(bo + n), b1 = __ldg(bo + n + 1);
                float* p = out + (size_t)m * CC + n;
                *(float2*)p = make_float2(acc[mt][nt][half * 2] + b0,
                                          acc[mt][nt][half * 2 + 1] + b1);
            }
}

extern "C" void kernel_launch(void* const* d_in, const int* in_sizes, int n_in,
                              void* d_out, int out_size)
{
    const float* x  = (const float*)d_in[0];
    const float* Wq = (const float*)d_in[1];
    const float* Wk = (const float*)d_in[2];
    const float* Wv = (const float*)d_in[3];
    const float* Wo = (const float*)d_in[4];
    const float* bo = (const float*)d_in[5];
    float* out = (float*)d_out;

    (void)in_sizes; (void)n_in; (void)out_size;

    // 1) QKV projections (R11 wide tile)
    qkv_mma<<<dim3(64, 24), 256>>>(x, Wq, Wk, Wv);

    // 2) Flash attention (register-P PV, 55,040 B dynamic smem)
    const int attn_smem = (128 * QS_STR + 32 * KP_STR + 64 * VP_STR) * 4;
    cudaFuncSetAttribute(attn_mma, cudaFuncAttributeMaxDynamicSharedMemorySize,
                         attn_smem);
    attn_mma<<<dim3(64, 16), 256, attn_smem>>>();

    // 3) Output projection + bias (R11 wide tile)
    proj_mma<<<dim3(64, 8), 256>>>(Wo, bo, out);
}

// round 16
// speedup vs baseline: 1.2745x; 1.2043x over previous
#include <cuda_runtime.h>
#include <math.h>

#define BB 4
#define TT 2048
#define CC 1024
#define HH 16
#define HS 64

// Scratch (no cudaMalloc allowed)
__device__ float g_q[(size_t)BB * HH * TT * HS];
__device__ float g_k[(size_t)BB * HH * TT * HS];
__device__ float g_v[(size_t)BB * HH * TT * HS];
__device__ float g_att[(size_t)BB * TT * CC];

__device__ __forceinline__ float tf32f(float x) {
    unsigned r;
    asm("cvt.rna.tf32.f32 %0, %1;" : "=r"(r) : "f"(x));
    return __uint_as_float(r);
}

__device__ __forceinline__ void mma_tf32(float* c, const unsigned* a, const unsigned* b) {
    asm volatile(
        "mma.sync.aligned.m16n8k8.row.col.f32.tf32.tf32.f32 "
        "{%0,%1,%2,%3},{%4,%5,%6,%7},{%8,%9},{%0,%1,%2,%3};"
        : "+f"(c[0]), "+f"(c[1]), "+f"(c[2]), "+f"(c[3])
        : "r"(a[0]), "r"(a[1]), "r"(a[2]), "r"(a[3]), "r"(b[0]), "r"(b[1]));
}

// ---------------------------------------------------------------------------
// Kernel 1: QKV projection, 1-term tf32 (A rounded at fill, no lo term).
// Wide tile 128x128 (2 heads/block). Warp grid 4x2, warp tile 32x64.
// grid = (M/128, 3 mats * 8 head-pairs).
// ---------------------------------------------------------------------------
__global__ __launch_bounds__(256, 2) void qkv_mma(
    const float* __restrict__ x,
    const float* __restrict__ Wq,
    const float* __restrict__ Wk,
    const float* __restrict__ Wv)
{
    __shared__ float As[128][36];   // tf32-rounded A
    __shared__ float Bh[128][37];   // tf32 B [n][k], 2 heads stacked

    const int tid    = threadIdx.x;
    const int warp   = tid >> 5;
    const int lane   = tid & 31;
    const int warp_m = warp >> 1;
    const int warp_n = warp & 1;
    const int mat    = blockIdx.y >> 3;
    const int hpair  = blockIdx.y & 7;
    const float* Wm  = (mat == 0 ? Wq : (mat == 1 ? Wk : Wv))
                       + (size_t)(2 * hpair) * CC * HS;
    float* outb      = (mat == 0 ? g_q : (mat == 1 ? g_k : g_v));
    const int m0     = blockIdx.x * 128;

    float acc[2][8][4];
    #pragma unroll
    for (int mt = 0; mt < 2; mt++)
        #pragma unroll
        for (int nt = 0; nt < 8; nt++)
            #pragma unroll
            for (int e = 0; e < 4; e++) acc[mt][nt][e] = 0.f;

    const int a_row = tid >> 3;
    const int a_kq  = tid & 7;
    const int b_kk  = tid >> 3;
    const int b_n8  = tid & 7;

    for (int k0 = 0; k0 < CC; k0 += 32) {
        #pragma unroll
        for (int c = 0; c < 4; c++) {
            int row = a_row + 32 * c;
            float4 v = *(const float4*)(x + (size_t)(m0 + row) * CC + k0 + a_kq * 4);
            As[row][a_kq * 4 + 0] = tf32f(v.x);
            As[row][a_kq * 4 + 1] = tf32f(v.y);
            As[row][a_kq * 4 + 2] = tf32f(v.z);
            As[row][a_kq * 4 + 3] = tf32f(v.w);
        }
        #pragma unroll
        for (int hp = 0; hp < 2; hp++) {
            const float* wp = Wm + (size_t)hp * CC * HS
                              + (size_t)(k0 + b_kk) * HS + b_n8 * 8;
            float4 v0 = *(const float4*)(wp);
            float4 v1 = *(const float4*)(wp + 4);
            float vv[8] = {v0.x, v0.y, v0.z, v0.w, v1.x, v1.y, v1.z, v1.w};
            #pragma unroll
            for (int e = 0; e < 8; e++)
                Bh[hp * 64 + b_n8 * 8 + e][b_kk] = tf32f(vv[e]);
        }
        __syncthreads();

        #pragma unroll
        for (int kk8 = 0; kk8 < 4; kk8++) {
            const int kc = kk8 * 8 + (lane & 3);
            unsigned ah[2][4], bh[8][2];
            #pragma unroll
            for (int mt = 0; mt < 2; mt++) {
                int r = warp_m * 32 + mt * 16 + (lane >> 2);
                ah[mt][0] = __float_as_uint(As[r][kc]);
                ah[mt][1] = __float_as_uint(As[r + 8][kc]);
                ah[mt][2] = __float_as_uint(As[r][kc + 4]);
                ah[mt][3] = __float_as_uint(As[r + 8][kc + 4]);
            }
            #pragma unroll
            for (int nt = 0; nt < 8; nt++) {
                int n = warp_n * 64 + nt * 8 + (lane >> 2);
                bh[nt][0] = __float_as_uint(Bh[n][kc]);
                bh[nt][1] = __float_as_uint(Bh[n][kc + 4]);
            }
            #pragma unroll
            for (int mt = 0; mt < 2; mt++)
                #pragma unroll
                for (int nt = 0; nt < 8; nt++)
                    mma_tf32(acc[mt][nt], ah[mt], bh[nt]);
        }
        __syncthreads();
    }

    #pragma unroll
    for (int mt = 0; mt < 2; mt++)
        #pragma unroll
        for (int nt = 0; nt < 8; nt++)
            #pragma unroll
            for (int half = 0; half < 2; half++) {
                int m = m0 + warp_m * 32 + mt * 16 + (lane >> 2) + half * 8;
                int col = warp_n * 64 + nt * 8 + (lane & 3) * 2;
                int head = 2 * hpair + (col >> 6);
                int hcol = col & (HS - 1);
                int b_ = m >> 11, t = m & (TT - 1);
                float* p = outb + ((size_t)((b_ * HH + head) * TT + t)) * HS + hcol;
                *(float2*)p = make_float2(acc[mt][nt][half * 2], acc[mt][nt][half * 2 + 1]);
            }
}

// ---------------------------------------------------------------------------
// Kernel 2: flash attention (unchanged R15 — protected win).
// Register-P PV, natural-V placement. QK 2-term / PV 1-term.
// grid = (B*H, 16). 8 warps x 16 q-rows. kv-block 32.
// smem: Qs 34,816 | Khp 9,472 | Vhp 10,752 = 55,040 B
// ---------------------------------------------------------------------------
#define QS_STR 68
#define KP_STR 74
#define VP_STR 42

__global__ __launch_bounds__(256) void attn_mma()
{
    extern __shared__ float sm[];
    float* Qs  = sm;                        // 128*68
    float* Khp = Qs + 128 * QS_STR;         // 32*74 (tf32 hi pairs)
    float* Vhp = Khp + 32 * KP_STR;         // 64*42 (tf32 hi, [d][s] natural)

    const int tid  = threadIdx.x;
    const int lane = tid & 31;
    const int warp = tid >> 5;
    const int bh   = blockIdx.x;
    const int qi   = (int)(gridDim.y - 1 - blockIdx.y);   // heavy tiles first
    const int b    = bh >> 4, h = bh & 15;
    const int q0g  = qi * 128;
    const int r_lo = warp * 16 + (lane >> 2);

    // Load Q tile (fp32)
    {
        int q = tid >> 1, dbase = (tid & 1) * 32;
        const float* qp = g_q + ((size_t)bh * TT + q0g + q) * HS + dbase;
        #pragma unroll
        for (int c = 0; c < 8; c++)
            *(float4*)&Qs[q * QS_STR + dbase + c * 4] = *(const float4*)(qp + c * 4);
    }

    float m_run[2] = {-1e30f, -1e30f};
    float l_run[2] = {0.f, 0.f};
    float acc_o[8][4];
    #pragma unroll
    for (int nt = 0; nt < 8; nt++)
        #pragma unroll
        for (int e = 0; e < 4; e++) acc_o[nt][e] = 0.f;

    const int nb   = 4 * qi + 4;
    const int wmax = q0g + warp * 16 + 15;

    for (int j = 0; j < nb; j++) {
        __syncthreads();    // prior block's reads done (covers Q store at j=0)
        // Fill K (tf32 hi, packed pairs) and V (transposed tf32 hi, NATURAL s)
        {
            int s = tid >> 3, d0 = (tid & 7) * 8;
            const float* kp = g_k + ((size_t)bh * TT + j * 32 + s) * HS + d0;
            const float* vp = g_v + ((size_t)bh * TT + j * 32 + s) * HS + d0;
            float4 ka = *(const float4*)(kp), kb = *(const float4*)(kp + 4);
            float kv[8] = {ka.x, ka.y, ka.z, ka.w, kb.x, kb.y, kb.z, kb.w};
            int kbase = s * KP_STR + d0;
            #pragma unroll
            for (int c = 0; c < 4; c++)
                *(float2*)&Khp[kbase + c * 2] =
                    make_float2(tf32f(kv[c]), tf32f(kv[c + 4]));
            float4 va = *(const float4*)(vp), vb = *(const float4*)(vp + 4);
            float vv[8] = {va.x, va.y, va.z, va.w, vb.x, vb.y, vb.z, vb.w};
            #pragma unroll
            for (int e = 0; e < 8; e++)
                Vhp[(d0 + e) * VP_STR + s] = tf32f(vv[e]);
        }
        __syncthreads();

        if (j * 32 <= wmax) {
            // ---- S = Q K^T (2-term: (Qh+Ql) x Kh; Q split at read) ----
            float accs[4][4];
            #pragma unroll
            for (int nt = 0; nt < 4; nt++)
                #pragma unroll
                for (int e = 0; e < 4; e++) accs[nt][e] = 0.f;

            #pragma unroll
            for (int k8 = 0; k8 < 8; k8++) {
                const int kc = k8 * 8 + (lane & 3);
                float q0 = Qs[r_lo * QS_STR + kc];
                float q1 = Qs[(r_lo + 8) * QS_STR + kc];
                float q2 = Qs[r_lo * QS_STR + kc + 4];
                float q3 = Qs[(r_lo + 8) * QS_STR + kc + 4];
                float h0 = tf32f(q0), h1 = tf32f(q1), h2 = tf32f(q2), h3 = tf32f(q3);
                unsigned ah[4] = {__float_as_uint(h0), __float_as_uint(h1),
                                  __float_as_uint(h2), __float_as_uint(h3)};
                unsigned al[4] = {__float_as_uint(q0 - h0), __float_as_uint(q1 - h1),
                                  __float_as_uint(q2 - h2), __float_as_uint(q3 - h3)};
                #pragma unroll
                for (int nt = 0; nt < 4; nt++) {
                    int n = nt * 8 + (lane >> 2);
                    float2 b2h = *(float2*)&Khp[n * KP_STR + k8 * 8 + (lane & 3) * 2];
                    unsigned bh2[2] = {__float_as_uint(b2h.x), __float_as_uint(b2h.y)};
                    mma_tf32(accs[nt], ah, bh2);
                    mma_tf32(accs[nt], al, bh2);
                }
            }

            // ---- online softmax (rows warp-local); build PV A-frags in regs
            const bool domask = (j >= 4 * qi);
            unsigned a_pv[4][4];   // [k-group nt][frag reg]
            #pragma unroll
            for (int half = 0; half < 2; half++) {
                const int tq = q0g + warp * 16 + (lane >> 2) + half * 8;
                float sv[4][2];
                float mx = -1e30f;
                #pragma unroll
                for (int nt = 0; nt < 4; nt++)
                    #pragma unroll
                    for (int e2 = 0; e2 < 2; e2++) {
                        float v = accs[nt][half * 2 + e2] * 0.125f;
                        int col = j * 32 + nt * 8 + (lane & 3) * 2 + e2;
                        if (domask && col > tq) v = -1e30f;
                        sv[nt][e2] = v;
                        mx = fmaxf(mx, v);
                    }
                mx = fmaxf(mx, __shfl_xor_sync(0xffffffffu, mx, 1));
                mx = fmaxf(mx, __shfl_xor_sync(0xffffffffu, mx, 2));
                float mn = fmaxf(m_run[half], mx);
                float cf = __expf(m_run[half] - mn);
                m_run[half] = mn;
                float ps = 0.f;
                #pragma unroll
                for (int nt = 0; nt < 4; nt++) {
                    #pragma unroll
                    for (int e2 = 0; e2 < 2; e2++) {
                        float p = __expf(sv[nt][e2] - mn);
                        sv[nt][e2] = p;
                        ps += p;
                    }
                    // A-frag: a[half] = col 2q value, a[2+half] = col 2q+1
                    a_pv[nt][half]     = __float_as_uint(tf32f(sv[nt][0]));
                    a_pv[nt][2 + half] = __float_as_uint(tf32f(sv[nt][1]));
                }
                ps += __shfl_xor_sync(0xffffffffu, ps, 1);
                ps += __shfl_xor_sync(0xffffffffu, ps, 2);
                l_run[half] = l_run[half] * cf + ps;
                #pragma unroll
                for (int nt = 0; nt < 8; nt++) {
                    acc_o[nt][half * 2] *= cf;
                    acc_o[nt][half * 2 + 1] *= cf;
                }
            }

            // ---- O += P V (1-term; A from registers, B natural-s float2) ----
            #pragma unroll
            for (int ntk = 0; ntk < 4; ntk++) {
                #pragma unroll
                for (int nt = 0; nt < 8; nt++) {
                    int n = nt * 8 + (lane >> 2);
                    float2 v2h = *(float2*)&Vhp[n * VP_STR + ntk * 8 + (lane & 3) * 2];
                    unsigned vh2[2] = {__float_as_uint(v2h.x), __float_as_uint(v2h.y)};
                    mma_tf32(acc_o[nt], a_pv[ntk], vh2);
                }
            }
        }
    }

    // Epilogue: normalize, write [B,T,C]
    #pragma unroll
    for (int half = 0; half < 2; half++) {
        float inv = 1.f / l_run[half];
        int tq = q0g + warp * 16 + (lane >> 2) + half * 8;
        #pragma unroll
        for (int nt = 0; nt < 8; nt++) {
            int col = h * HS + nt * 8 + (lane & 3) * 2;
            float* op = g_att + ((size_t)(b * TT + tq)) * CC + col;
            *(float2*)op = make_float2(acc_o[nt][half * 2] * inv,
                                       acc_o[nt][half * 2 + 1] * inv);
        }
    }
}

// ---------------------------------------------------------------------------
// Kernel 3: output projection, 1-term tf32 (A rounded at fill).
// Wide tile 128x128, warp tile 32x64. grid = (M/128, N/128).
// ---------------------------------------------------------------------------
__global__ __launch_bounds__(256, 2) void proj_mma(
    const float* __restrict__ Wo,
    const float* __restrict__ bo,
    float* __restrict__ out)
{
    __shared__ float As[128][36];
    __shared__ float Bh[128][36];

    const int tid    = threadIdx.x;
    const int warp   = tid >> 5;
    const int lane   = tid & 31;
    const int warp_m = warp >> 1;
    const int warp_n = warp & 1;
    const int m0     = blockIdx.x * 128;
    const int n0     = blockIdx.y * 128;

    float acc[2][8][4];
    #pragma unroll
    for (int mt = 0; mt < 2; mt++)
        #pragma unroll
        for (int nt = 0; nt < 8; nt++)
            #pragma unroll
            for (int e = 0; e < 4; e++) acc[mt][nt][e] = 0.f;

    const int a_row = tid >> 3;
    const int a_kq  = tid & 7;
    const int b_n   = tid >> 2;
    const int b_kq  = tid & 3;

    for (int k0 = 0; k0 < CC; k0 += 32) {
        #pragma unroll
        for (int c = 0; c < 4; c++) {
            int row = a_row + 32 * c;
            float4 v = *(const float4*)(g_att + (size_t)(m0 + row) * CC + k0 + a_kq * 4);
            As[row][a_kq * 4 + 0] = tf32f(v.x);
            As[row][a_kq * 4 + 1] = tf32f(v.y);
            As[row][a_kq * 4 + 2] = tf32f(v.z);
            As[row][a_kq * 4 + 3] = tf32f(v.w);
        }
        #pragma unroll
        for (int np = 0; np < 2; np++) {
            int n = np * 64 + b_n;
            const float* wp = Wo + (size_t)(n0 + n) * CC + k0 + b_kq * 8;
            float4 v0 = *(const float4*)(wp);
            float4 v1 = *(const float4*)(wp + 4);
            float vv[8] = {v0.x, v0.y, v0.z, v0.w, v1.x, v1.y, v1.z, v1.w};
            #pragma unroll
            for (int e = 0; e < 8; e++)
                Bh[n][b_kq * 8 + e] = tf32f(vv[e]);
        }
        __syncthreads();

        #pragma unroll
        for (int kk8 = 0; kk8 < 4; kk8++) {
            const int kc = kk8 * 8 + (lane & 3);
            unsigned ah[2][4], bh[8][2];
            #pragma unroll
            for (int mt = 0; mt < 2; mt++) {
                int r = warp_m * 32 + mt * 16 + (lane >> 2);
                ah[mt][0] = __float_as_uint(As[r][kc]);
                ah[mt][1] = __float_as_uint(As[r + 8][kc]);
                ah[mt][2] = __float_as_uint(As[r][kc + 4]);
                ah[mt][3] = __float_as_uint(As[r + 8][kc + 4]);
            }
            #pragma unroll
            for (int nt = 0; nt < 8; nt++) {
                int n = warp_n * 64 + nt * 8 + (lane >> 2);
                bh[nt][0] = __float_as_uint(Bh[n][kc]);
                bh[nt][1] = __float_as_uint(Bh[n][kc + 4]);
            }
            #pragma unroll
            for (int mt = 0; mt < 2; mt++)
                #pragma unroll
                for (int nt = 0; nt < 8; nt++)
                    mma_tf32(acc[mt][nt], ah[mt], bh[nt]);
        }
        __syncthreads();
    }

    #pragma unroll
    for (int mt = 0; mt < 2; mt++)
        #pragma unroll
        for (int nt = 0; nt < 8; nt++)
            #pragma unroll
            for (int half = 0; half < 2; half++) {
                int m = m0 + warp_m * 32 + mt * 16 + (lane >> 2) + half * 8;
                int n = n0 + warp_n * 64 + nt * 8 + (lane & 3) * 2;
                float b0 = __ldg(bo + n), b1 = __ldg(bo + n + 1);
                float* p = out + (size_t)m * CC + n;
                *(float2*)p = make_float2(acc[mt][nt][half * 2] + b0,
                                          acc[mt][nt][half * 2 + 1] + b1);
            }
}

extern "C" void kernel_launch(void* const* d_in, const int* in_sizes, int n_in,
                              void* d_out, int out_size)
{
    const float* x  = (const float*)d_in[0];
    const float* Wq = (const float*)d_in[1];
    const float* Wk = (const float*)d_in[2];
    const float* Wv = (const float*)d_in[3];
    const float* Wo = (const float*)d_in[4];
    const float* bo = (const float*)d_in[5];
    float* out = (float*)d_out;

    (void)in_sizes; (void)n_in; (void)out_size;

    // 1) QKV projections (1-term tf32, wide tile)
    qkv_mma<<<dim3(64, 24), 256>>>(x, Wq, Wk, Wv);

    // 2) Flash attention (register-P PV, 55,040 B dynamic smem)
    const int attn_smem = (128 * QS_STR + 32 * KP_STR + 64 * VP_STR) * 4;
    cudaFuncSetAttribute(attn_mma, cudaFuncAttributeMaxDynamicSharedMemorySize,
                         attn_smem);
    attn_mma<<<dim3(64, 16), 256, attn_smem>>>();

    // 3) Output projection + bias (1-term tf32, wide tile)
    proj_mma<<<dim3(64, 8), 256>>>(Wo, bo, out);
}